// round 3
// baseline (speedup 1.0000x reference)
#include <cuda_runtime.h>

// out[i] = sum_b sum_j x1[b,j] * x2[b,(i-j) mod 1024]

#define BSZ 128
#define D   1024
#define DMASK 1023

typedef unsigned long long u64;

__device__ float g_partial[BSZ * D];   // per-batch conv results
__device__ unsigned g_counter = 0;     // monotonically increasing ticket

__device__ __forceinline__ u64 as_u64(float2 v) { return *reinterpret_cast<u64*>(&v); }

__device__ __forceinline__ u64 fma_x2(u64 a, u64 b, u64 c) {
    u64 d;
    asm("fma.rn.f32x2 %0, %1, %2, %3;" : "=l"(d) : "l"(a), "l"(b), "l"(c));
    return d;
}

__global__ void __launch_bounds__(256, 1)
conv_fused_kernel(const float* __restrict__ x1, const float* __restrict__ x2,
                  float* __restrict__ out) {
    __shared__ __align__(16) float s1d[2 * D];  // duplicated x1: s1d[2j]=s1d[2j+1]=x1[j]
    __shared__ __align__(16) float s2[D];
    __shared__ float red[256];

    const int b   = blockIdx.x;
    const int tid = threadIdx.x;

    // ---- stage ----
    {
        const float4 v1 = reinterpret_cast<const float4*>(x1 + b * D)[tid];
        const float4 v2 = reinterpret_cast<const float4*>(x2 + b * D)[tid];
        reinterpret_cast<float4*>(s2)[tid] = v2;
        float4* s1v = reinterpret_cast<float4*>(s1d) + tid * 2;
        s1v[0] = make_float4(v1.x, v1.x, v1.y, v1.y);
        s1v[1] = make_float4(v1.z, v1.z, v1.w, v1.w);
    }
    __syncthreads();

    const int i0 = tid * 4;  // outputs i0..i0+3

    // Window V[k] = s2[(i0 - 4 - j + k) & DMASK] at chunk start j.
    // E[p] = (V[2p],V[2p+1])  (even-aligned packed pairs)
    // O[p] = (V[2p+1],V[2p+2]) (odd-aligned packed pairs)
    float2 E0, E1, E2, E3, O0, O1, O2;
    {
        const float4 q0 = *reinterpret_cast<const float4*>(&s2[(i0 - 4) & DMASK]);
        const float4 q1 = *reinterpret_cast<const float4*>(&s2[i0]);
        E0 = make_float2(q0.x, q0.y); E1 = make_float2(q0.z, q0.w);
        E2 = make_float2(q1.x, q1.y); E3 = make_float2(q1.z, q1.w);
        O0 = make_float2(q0.y, q0.z); O1 = make_float2(q0.w, q1.x);
        O2 = make_float2(q1.y, q1.z);
    }

    u64 P0 = 0, P1 = 0;  // packed (acc0,acc1), (acc2,acc3)
    const float2* s1d2 = reinterpret_cast<const float2*>(s1d);

    #pragma unroll 8
    for (int j = 0; j < D; j += 4) {
        const u64 A0 = as_u64(s1d2[j + 0]);   // (a_j, a_j) broadcast
        const u64 A1 = as_u64(s1d2[j + 1]);
        const u64 A2 = as_u64(s1d2[j + 2]);
        const u64 A3 = as_u64(s1d2[j + 3]);

        P0 = fma_x2(A0, as_u64(E2), P0);  P1 = fma_x2(A0, as_u64(E3), P1);
        P0 = fma_x2(A1, as_u64(O1), P0);  P1 = fma_x2(A1, as_u64(O2), P1);
        P0 = fma_x2(A2, as_u64(E1), P0);  P1 = fma_x2(A2, as_u64(E2), P1);
        P0 = fma_x2(A3, as_u64(O0), P0);  P1 = fma_x2(A3, as_u64(O1), P1);

        // shift window down by 4: refill V[-4..-1] (16B aligned, no wrap straddle)
        const float4 nv = *reinterpret_cast<const float4*>(&s2[(i0 - j - 8) & DMASK]);
        const float2 nE0 = make_float2(nv.x, nv.y);
        const float2 nE1 = make_float2(nv.z, nv.w);
        const float2 nO0 = make_float2(nE0.y, nE1.x);
        const float2 nO1 = make_float2(nE1.y, E0.x);
        O2 = O0; O1 = nO1; O0 = nO0;
        E3 = E1; E2 = E0; E1 = nE1; E0 = nE0;
    }

    {
        const float2 p0 = *reinterpret_cast<float2*>(&P0);
        const float2 p1 = *reinterpret_cast<float2*>(&P1);
        *reinterpret_cast<float4*>(&g_partial[b * D + i0]) =
            make_float4(p0.x, p0.y, p1.x, p1.y);
    }

    // ---- cross-CTA barrier (replay-safe ticket) ----
    __syncthreads();
    if (tid == 0) {
        __threadfence();  // release g_partial writes
        const unsigned old    = atomicAdd(&g_counter, 1u);
        const unsigned target = old - (old & (BSZ - 1)) + BSZ;
        unsigned cur;
        do {
            asm volatile("ld.global.acquire.gpu.u32 %0, [%1];"
                         : "=r"(cur) : "l"(&g_counter));
        } while ((int)(cur - target) < 0);
    }
    __syncthreads();

    // ---- fused deterministic reduction: CTA b owns outputs [8b, 8b+8) ----
    {
        const int i    = blockIdx.x * 8 + (tid & 7);
        const int brow = tid >> 3;  // 0..31
        float s = __ldcg(&g_partial[(brow      ) * D + i])
                + __ldcg(&g_partial[(brow + 32 ) * D + i])
                + __ldcg(&g_partial[(brow + 64 ) * D + i])
                + __ldcg(&g_partial[(brow + 96 ) * D + i]);
        red[tid] = s;
        __syncthreads();
        if (tid < 8) {
            float t = 0.f;
            #pragma unroll
            for (int m = 0; m < 32; m++) t += red[tid + 8 * m];
            out[blockIdx.x * 8 + tid] = t;
        }
    }
}

extern "C" void kernel_launch(void* const* d_in, const int* in_sizes, int n_in,
                              void* d_out, int out_size) {
    const float* x1  = (const float*)d_in[0];  // input1: (128, 1024) fp32
    const float* x2  = (const float*)d_in[1];  // input2: (128, 1024) fp32
    float*       out = (float*)d_out;          // (1,1,1024) fp32

    conv_fused_kernel<<<BSZ, 256>>>(x1, x2, out);
}